// round 2
// baseline (speedup 1.0000x reference)
#include <cuda_runtime.h>

#define NN 50000
#define NE 200000
#define F0 512
#define F1 2048
#define F2 256
#define F3 64

// ---------------- scratch (device globals; no allocs allowed) ----------------
__device__ float g_deg[NN];
__device__ float g_dinv[NN];
__device__ int   g_idx[2 * NE];     // [row..., col...] as int32
__device__ int   g_flag32;          // 1 => input edge_index is int32
__device__ float g_agg0[(size_t)NN * F0];   // A @ x          (102 MB)
__device__ float g_h1  [(size_t)NN * F1];   // layer-1 output (410 MB)
__device__ float g_t2  [(size_t)NN * F2];   // h1 @ W2        (51 MB)
__device__ float g_a2  [(size_t)NN * F2];   // A @ t2         (51 MB)
__device__ float g_t3  [(size_t)NN * F3];   // h2 @ W3        (13 MB)

// ---------------- small setup kernels ----------------
__global__ void k_init() {
    int i = blockIdx.x * blockDim.x + threadIdx.x;
    if (i < NN) g_deg[i] = 1.0f;          // self-loop weight folded into init
    if (i == 0) g_flag32 = 0;
}

// Detect int32 vs int64 edge_index: if int64 (values in [0, 50000)), every odd
// int32 word is the zero high-half. If int32, odd words are random node ids —
// 128 consecutive zeros is impossible.
__global__ void k_detect(const int* ei32) {
    int w = ei32[2 * threadIdx.x + 1];
    if (w != 0) atomicOr(&g_flag32, 1);
}

__global__ void k_convert(const void* ei) {
    int i = blockIdx.x * blockDim.x + threadIdx.x;
    if (i >= 2 * NE) return;
    int v;
    if (g_flag32) v = ((const int*)ei)[i];
    else          v = (int)(((const long long*)ei)[i]);
    g_idx[i] = v;
}

__global__ void k_deg(const float* __restrict__ ew) {
    int e = blockIdx.x * blockDim.x + threadIdx.x;
    if (e >= NE) return;
    atomicAdd(&g_deg[g_idx[NE + e]], ew[e]);
}

__global__ void k_dinv() {
    int i = blockIdx.x * blockDim.x + threadIdx.x;
    if (i >= NN) return;
    float d = g_deg[i];
    g_dinv[i] = (d > 0.0f) ? rsqrtf(d) : 0.0f;
}

// ---------------- aggregation: out = A_norm @ in ----------------
// Self-loop term doubles as initializer: out[i] = dinv[i]^2 * in[i]
template<int F>
__global__ void k_selfloop(const float* __restrict__ in, float* __restrict__ out) {
    const int total = NN * (F / 4);
    int i = blockIdx.x * blockDim.x + threadIdx.x;
    if (i >= total) return;
    int node = i / (F / 4);
    float d = g_dinv[node];
    float s = d * d;
    float4 v = ((const float4*)in)[i];
    v.x *= s; v.y *= s; v.z *= s; v.w *= s;
    ((float4*)out)[i] = v;
}

template<int F>
__global__ void k_edgeagg(const float* __restrict__ ew,
                          const float* __restrict__ in,
                          float* __restrict__ out) {
    constexpr int TPE = F / 4;                 // threads per edge (float4 lanes)
    int t = blockIdx.x * blockDim.x + threadIdx.x;
    int e = t / TPE;
    if (e >= NE) return;
    int f4 = t % TPE;
    int r = g_idx[e];
    int c = g_idx[NE + e];
    float nrm = g_dinv[r] * ew[e] * g_dinv[c];
    float4 v = ((const float4*)(in + (size_t)r * F))[f4];
    float* o = out + (size_t)c * F + f4 * 4;
    atomicAdd(o + 0, nrm * v.x);
    atomicAdd(o + 1, nrm * v.y);
    atomicAdd(o + 2, nrm * v.z);
    atomicAdd(o + 3, nrm * v.w);
}

// ---------------- epilogue: x = relu(x + b), vectorized ----------------
template<int F>
__global__ void k_biasrelu(float* __restrict__ x, const float* __restrict__ b) {
    const int total = NN * (F / 4);
    int i = blockIdx.x * blockDim.x + threadIdx.x;
    if (i >= total) return;
    int f4 = i % (F / 4);
    float4 v  = ((float4*)x)[i];
    float4 bb = ((const float4*)b)[f4];
    v.x = fmaxf(v.x + bb.x, 0.0f);
    v.y = fmaxf(v.y + bb.y, 0.0f);
    v.z = fmaxf(v.z + bb.z, 0.0f);
    v.w = fmaxf(v.w + bb.w, 0.0f);
    ((float4*)x)[i] = v;
}

// ---------------- SGEMM: C[MxN] = A[MxK] @ B[KxN] (row-major) ----------------
// 128x128 block tile, BK=16, 8x8 per-thread tile, double-buffered smem,
// register-staged global prefetch, ONE __syncthreads per mainloop iter.
// EPI 0: C = AB.  EPI 1: C = leaky_relu(AB + bias, 0.01)
// Requires: K % 16 == 0, N % 4 == 0.
template<int EPI>
__global__ __launch_bounds__(256)
void sgemm128(int M, int N, int K,
              const float* __restrict__ A, const float* __restrict__ B,
              const float* __restrict__ bias, float* __restrict__ C) {
    constexpr int BM = 128, BN = 128, BK = 16, TM = 8, TN = 8;
    __shared__ float As[2][BK][BM];     // transposed A tile: As[k][m]
    __shared__ float Bs[2][BK][BN];

    const int tid = threadIdx.x;
    const int tx  = tid % 16;          // 16 col-groups
    const int ty  = tid / 16;          // 16 row-groups
    const int rowBase = blockIdx.y * BM;
    const int colBase = blockIdx.x * BN;

    // A tile loader: 128 rows x 16 cols; thread loads rows aRow & aRow+64
    const int aRow  = tid / 4;               // 0..63
    const int aCol4 = (tid % 4) * 4;         // 0,4,8,12
    // B tile loader: 16 rows x 128 cols; thread loads rows bRow & bRow+8
    const int bRow  = tid / 32;              // 0..7
    const int bCol4 = (tid % 32) * 4;        // 0..124

    const bool aOk0 = (rowBase + aRow) < M;
    const bool aOk1 = (rowBase + aRow + 64) < M;
    const bool bOk  = (colBase + bCol4) < N;

    float acc[TM][TN];
#pragma unroll
    for (int i = 0; i < TM; i++)
#pragma unroll
        for (int j = 0; j < TN; j++) acc[i][j] = 0.0f;

    const float4 z4 = make_float4(0.f, 0.f, 0.f, 0.f);

    // ---- load first tile into buffer 0 ----
    {
        float4 a0 = aOk0 ? *(const float4*)(A + (size_t)(rowBase + aRow) * K + aCol4) : z4;
        float4 a1 = aOk1 ? *(const float4*)(A + (size_t)(rowBase + aRow + 64) * K + aCol4) : z4;
        As[0][aCol4 + 0][aRow]      = a0.x;
        As[0][aCol4 + 1][aRow]      = a0.y;
        As[0][aCol4 + 2][aRow]      = a0.z;
        As[0][aCol4 + 3][aRow]      = a0.w;
        As[0][aCol4 + 0][aRow + 64] = a1.x;
        As[0][aCol4 + 1][aRow + 64] = a1.y;
        As[0][aCol4 + 2][aRow + 64] = a1.z;
        As[0][aCol4 + 3][aRow + 64] = a1.w;

        float4 b0 = bOk ? *(const float4*)(B + (size_t)bRow * N + colBase + bCol4) : z4;
        float4 b1 = bOk ? *(const float4*)(B + (size_t)(bRow + 8) * N + colBase + bCol4) : z4;
        *(float4*)&Bs[0][bRow][bCol4]     = b0;
        *(float4*)&Bs[0][bRow + 8][bCol4] = b1;
    }
    __syncthreads();

    int cur = 0;
    for (int k0 = 0; k0 < K; k0 += BK) {
        const bool hasNext = (k0 + BK) < K;
        float4 na0 = z4, na1 = z4, nb0 = z4, nb1 = z4;
        if (hasNext) {
            const int kn = k0 + BK;
            if (aOk0) na0 = *(const float4*)(A + (size_t)(rowBase + aRow) * K + kn + aCol4);
            if (aOk1) na1 = *(const float4*)(A + (size_t)(rowBase + aRow + 64) * K + kn + aCol4);
            if (bOk) {
                nb0 = *(const float4*)(B + (size_t)(kn + bRow) * N + colBase + bCol4);
                nb1 = *(const float4*)(B + (size_t)(kn + bRow + 8) * N + colBase + bCol4);
            }
        }

        // ---- compute on buffer `cur` ----
        float ar[TM], br[TN];
#pragma unroll
        for (int kk = 0; kk < BK; kk++) {
#pragma unroll
            for (int i = 0; i < TM; i++) ar[i] = As[cur][kk][ty * TM + i];
#pragma unroll
            for (int j = 0; j < TN; j++) br[j] = Bs[cur][kk][tx * TN + j];
#pragma unroll
            for (int i = 0; i < TM; i++)
#pragma unroll
                for (int j = 0; j < TN; j++) acc[i][j] += ar[i] * br[j];
        }

        if (hasNext) {
            const int nxt = cur ^ 1;
            As[nxt][aCol4 + 0][aRow]      = na0.x;
            As[nxt][aCol4 + 1][aRow]      = na0.y;
            As[nxt][aCol4 + 2][aRow]      = na0.z;
            As[nxt][aCol4 + 3][aRow]      = na0.w;
            As[nxt][aCol4 + 0][aRow + 64] = na1.x;
            As[nxt][aCol4 + 1][aRow + 64] = na1.y;
            As[nxt][aCol4 + 2][aRow + 64] = na1.z;
            As[nxt][aCol4 + 3][aRow + 64] = na1.w;
            *(float4*)&Bs[nxt][bRow][bCol4]     = nb0;
            *(float4*)&Bs[nxt][bRow + 8][bCol4] = nb1;
            __syncthreads();
            cur = nxt;
        }
    }

#pragma unroll
    for (int i = 0; i < TM; i++) {
        int r = rowBase + ty * TM + i;
        if (r >= M) continue;
#pragma unroll
        for (int j = 0; j < TN; j += 4) {
            int c = colBase + tx * TN + j;
            if (c >= N) continue;               // N is a multiple of 4
            float4 v = make_float4(acc[i][j], acc[i][j + 1], acc[i][j + 2], acc[i][j + 3]);
            if (EPI == 1) {
                const float4 bb = *(const float4*)(bias + c);
                v.x += bb.x; v.y += bb.y; v.z += bb.z; v.w += bb.w;
                v.x = (v.x > 0.f) ? v.x : 0.01f * v.x;
                v.y = (v.y > 0.f) ? v.y : 0.01f * v.y;
                v.z = (v.z > 0.f) ? v.z : 0.01f * v.z;
                v.w = (v.w > 0.f) ? v.w : 0.01f * v.w;
            }
            *(float4*)(C + (size_t)r * N + c) = v;
        }
    }
}

// ---------------- launcher ----------------
extern "C" void kernel_launch(void* const* d_in, const int* in_sizes, int n_in,
                              void* d_out, int out_size) {
    const float* x  = (const float*)d_in[0];
    const void*  ei = d_in[1];
    const float* ew = (const float*)d_in[2];
    const float* W1 = (const float*)d_in[3];
    const float* b1 = (const float*)d_in[4];
    const float* W2 = (const float*)d_in[5];
    const float* b2 = (const float*)d_in[6];
    const float* W3 = (const float*)d_in[7];
    const float* b3 = (const float*)d_in[8];
    float* out = (float*)d_out;

    float *p_agg0, *p_h1, *p_t2, *p_a2, *p_t3;
    cudaGetSymbolAddress((void**)&p_agg0, g_agg0);
    cudaGetSymbolAddress((void**)&p_h1,   g_h1);
    cudaGetSymbolAddress((void**)&p_t2,   g_t2);
    cudaGetSymbolAddress((void**)&p_a2,   g_a2);
    cudaGetSymbolAddress((void**)&p_t3,   g_t3);

    // normalization
    k_init<<<(NN + 255) / 256, 256>>>();
    k_detect<<<1, 128>>>((const int*)ei);
    k_convert<<<(2 * NE + 255) / 256, 256>>>(ei);
    k_deg<<<(NE + 255) / 256, 256>>>(ew);
    k_dinv<<<(NN + 255) / 256, 256>>>();

    // ---- layer 1: aggregate(512) first, then GEMM + bias + leaky ----
    // A(XW) == (AX)W  -> aggregate in the 512-dim space (4x less traffic)
    k_selfloop<F0><<<(NN * (F0 / 4) + 255) / 256, 256>>>(x, p_agg0);
    k_edgeagg<F0><<<(NE * (F0 / 4) + 255) / 256, 256>>>(ew, x, p_agg0);
    sgemm128<1><<<dim3((F1 + 127) / 128, (NN + 127) / 128), 256>>>(
        NN, F1, F0, p_agg0, W1, b1, p_h1);

    // ---- layer 2: GEMM(2048->256) first, then aggregate + bias + relu ----
    sgemm128<0><<<dim3((F2 + 127) / 128, (NN + 127) / 128), 256>>>(
        NN, F2, F1, p_h1, W2, nullptr, p_t2);
    k_selfloop<F2><<<(NN * (F2 / 4) + 255) / 256, 256>>>(p_t2, p_a2);
    k_edgeagg<F2><<<(NE * (F2 / 4) + 255) / 256, 256>>>(ew, p_t2, p_a2);
    k_biasrelu<F2><<<(NN * (F2 / 4) + 255) / 256, 256>>>(p_a2, b2);

    // ---- layer 3: GEMM(256->64) first, then aggregate + bias + relu ----
    sgemm128<0><<<dim3((F3 + 127) / 128, (NN + 127) / 128), 256>>>(
        NN, F3, F2, p_a2, W3, nullptr, p_t3);
    k_selfloop<F3><<<(NN * (F3 / 4) + 255) / 256, 256>>>(p_t3, out);
    k_edgeagg<F3><<<(NE * (F3 / 4) + 255) / 256, 256>>>(ew, p_t3, out);
    k_biasrelu<F3><<<(NN * (F3 / 4) + 255) / 256, 256>>>(out, b3);
}

// round 12
// speedup vs baseline: 1.1735x; 1.1735x over previous
#include <cuda_runtime.h>
#include <cuda_bf16.h>
#include <cstdint>

#define NN 50000
#define NE 200000
#define F0 512
#define F1 2048
#define F2 256
#define F3 64

// ---------------- scratch (device globals; no allocs allowed) ----------------
__device__ float g_deg[NN];
__device__ float g_dinv[NN];
__device__ float g_nrm[NE];         // per-edge normalized weight
__device__ int   g_idx[2 * NE];
__device__ int   g_flag32;

__device__ float         g_agg0[(size_t)NN * F0];          // A @ x (fp32, atomics)
__device__ __nv_bfloat16 g_a0hi[(size_t)NN * F0];
__device__ __nv_bfloat16 g_a0lo[(size_t)NN * F0];
__device__ __nv_bfloat16 g_h1hi[(size_t)NN * F1];          // layer-1 out (bf16 split)
__device__ __nv_bfloat16 g_h1lo[(size_t)NN * F1];
__device__ float         g_t2[(size_t)NN * F2];            // h1 @ W2 (fp32)
__device__ float         g_a2[(size_t)NN * F2];            // A @ t2 (fp32, atomics)
__device__ __nv_bfloat16 g_a2hi[(size_t)NN * F2];
__device__ __nv_bfloat16 g_a2lo[(size_t)NN * F2];
__device__ float         g_t3[(size_t)NN * F3];            // h2 @ W3 (fp32)
__device__ __nv_bfloat16 g_w1hi[F0 * F1], g_w1lo[F0 * F1];
__device__ __nv_bfloat16 g_w2hi[F1 * F2], g_w2lo[F1 * F2];
__device__ __nv_bfloat16 g_w3hi[F2 * F3], g_w3lo[F2 * F3];

// ---------------- setup ----------------
__global__ void k_init() {
    int i = blockIdx.x * blockDim.x + threadIdx.x;
    if (i < NN) g_deg[i] = 1.0f;          // self-loop weight folded in
    if (i == 0) g_flag32 = 0;
}

// int64 edge_index has zero high halves (ids < 50000); int32 would make many
// odd words nonzero. 128 consecutive zero odd-words => int64.
__global__ void k_detect(const int* ei32) {
    int w = ei32[2 * threadIdx.x + 1];
    if (w != 0) atomicOr(&g_flag32, 1);
}

__global__ void k_convert(const void* ei) {
    int i = blockIdx.x * blockDim.x + threadIdx.x;
    if (i >= 2 * NE) return;
    int v;
    if (g_flag32) v = ((const int*)ei)[i];
    else          v = (int)(((const long long*)ei)[i]);
    g_idx[i] = v;
}

__global__ void k_deg(const float* __restrict__ ew) {
    int e = blockIdx.x * blockDim.x + threadIdx.x;
    if (e >= NE) return;
    atomicAdd(&g_deg[g_idx[NE + e]], ew[e]);
}

__global__ void k_dinv() {
    int i = blockIdx.x * blockDim.x + threadIdx.x;
    if (i >= NN) return;
    float d = g_deg[i];
    g_dinv[i] = (d > 0.0f) ? rsqrtf(d) : 0.0f;
}

__global__ void k_norm(const float* __restrict__ ew) {
    int e = blockIdx.x * blockDim.x + threadIdx.x;
    if (e >= NE) return;
    g_nrm[e] = g_dinv[g_idx[e]] * ew[e] * g_dinv[g_idx[NE + e]];
}

// ---------------- fp32 -> bf16 hi/lo split ----------------
__device__ __forceinline__ void split2(float v0, float v1,
                                       __nv_bfloat162& H, __nv_bfloat162& L) {
    __nv_bfloat16 h0 = __float2bfloat16(v0);
    __nv_bfloat16 h1 = __float2bfloat16(v1);
    H.x = h0; H.y = h1;
    L.x = __float2bfloat16(v0 - __bfloat162float(h0));
    L.y = __float2bfloat16(v1 - __bfloat162float(h1));
}

__global__ void k_split(const float* __restrict__ src,
                        __nv_bfloat16* __restrict__ hi,
                        __nv_bfloat16* __restrict__ lo, int n4) {
    int i = blockIdx.x * blockDim.x + threadIdx.x;
    if (i >= n4) return;
    float4 v = ((const float4*)src)[i];
    __nv_bfloat162 H0, L0, H1, L1;
    split2(v.x, v.y, H0, L0);
    split2(v.z, v.w, H1, L1);
    ((__nv_bfloat162*)hi)[2 * i] = H0;  ((__nv_bfloat162*)hi)[2 * i + 1] = H1;
    ((__nv_bfloat162*)lo)[2 * i] = L0;  ((__nv_bfloat162*)lo)[2 * i + 1] = L1;
}

// ---------------- aggregation ----------------
// Self-loop term doubles as initializer: out[i] = dinv[i]^2 * in[i]
template<int F>
__global__ void k_selfloop(const float* __restrict__ in, float* __restrict__ out) {
    const int total = NN * (F / 4);
    int i = blockIdx.x * blockDim.x + threadIdx.x;
    if (i >= total) return;
    int node = i / (F / 4);
    float d = g_dinv[node];
    float s = d * d;
    float4 v = ((const float4*)in)[i];
    v.x *= s; v.y *= s; v.z *= s; v.w *= s;
    ((float4*)out)[i] = v;
}

template<int F>
__global__ void k_edgeagg(const float* __restrict__ in, float* __restrict__ out) {
    constexpr int TPE = F / 4;
    int tt = blockIdx.x * blockDim.x + threadIdx.x;
    int e = tt / TPE;
    if (e >= NE) return;
    int f4 = tt % TPE;
    int r = g_idx[e];
    int c = g_idx[NE + e];
    float nrm = g_nrm[e];
    float4 v = ((const float4*)(in + (size_t)r * F))[f4];
    float* o = out + (size_t)c * F + f4 * 4;
    asm volatile("red.global.add.v4.f32 [%0], {%1,%2,%3,%4};"
                 :: "l"(o), "f"(nrm * v.x), "f"(nrm * v.y),
                    "f"(nrm * v.z), "f"(nrm * v.w) : "memory");
}

// x = relu(x + b) in place (final layer, fp32 out)
template<int F>
__global__ void k_biasrelu(float* __restrict__ x, const float* __restrict__ b) {
    const int total = NN * (F / 4);
    int i = blockIdx.x * blockDim.x + threadIdx.x;
    if (i >= total) return;
    int f4 = i % (F / 4);
    float4 v  = ((float4*)x)[i];
    float4 bb = ((const float4*)b)[f4];
    v.x = fmaxf(v.x + bb.x, 0.0f);
    v.y = fmaxf(v.y + bb.y, 0.0f);
    v.z = fmaxf(v.z + bb.z, 0.0f);
    v.w = fmaxf(v.w + bb.w, 0.0f);
    ((float4*)x)[i] = v;
}

// relu(x + b) -> bf16 hi/lo split (feeds next GEMM)
template<int F>
__global__ void k_biassplit(const float* __restrict__ x, const float* __restrict__ b,
                            __nv_bfloat16* __restrict__ hi, __nv_bfloat16* __restrict__ lo) {
    const int total = NN * (F / 4);
    int i = blockIdx.x * blockDim.x + threadIdx.x;
    if (i >= total) return;
    int f4 = i % (F / 4);
    float4 v  = ((const float4*)x)[i];
    float4 bb = ((const float4*)b)[f4];
    v.x = fmaxf(v.x + bb.x, 0.0f);
    v.y = fmaxf(v.y + bb.y, 0.0f);
    v.z = fmaxf(v.z + bb.z, 0.0f);
    v.w = fmaxf(v.w + bb.w, 0.0f);
    __nv_bfloat162 H0, L0, H1, L1;
    split2(v.x, v.y, H0, L0);
    split2(v.z, v.w, H1, L1);
    ((__nv_bfloat162*)hi)[2 * i] = H0;  ((__nv_bfloat162*)hi)[2 * i + 1] = H1;
    ((__nv_bfloat162*)lo)[2 * i] = L0;  ((__nv_bfloat162*)lo)[2 * i + 1] = L1;
}

// ---------------- bf16x3 tensor-core GEMM ----------------
// C[M,N] = A[M,K] @ B[K,N], fp32-equivalent accuracy via 3-term bf16 split:
//   A*B ~= Ahi*Bhi + Alo*Bhi + Ahi*Blo, run as ONE GEMM over virtual K'=3K
//   (segment s picks the tile source; K % 32 == 0 so chunks never straddle).
// Block 128xBN, BK=32 (two m16n8k16 k-steps), 8 warps (4x2), warp tile 32x(BN/2).
// smem: 16-bit pairs along k packed in 32-bit words, MN-major, row stride 20
// words -> all fragment LDS conflict-free.
// EPI 0: Cf = AB (fp32).  EPI 1: leaky_relu(AB + bias) split -> Chi/Clo bf16.
template<int BN, int EPI>
__global__ __launch_bounds__(256, 1)
void gemm_b3(int M, int N, int K,
             const __nv_bfloat16* __restrict__ Ahi, const __nv_bfloat16* __restrict__ Alo,
             const __nv_bfloat16* __restrict__ Bhi, const __nv_bfloat16* __restrict__ Blo,
             const float* __restrict__ bias, float* __restrict__ Cf,
             __nv_bfloat16* __restrict__ Chi, __nv_bfloat16* __restrict__ Clo) {
    constexpr int BM = 128, BK = 32, STR = 20, NT = BN / 16;
    __shared__ uint32_t As[2][BM * STR];
    __shared__ uint32_t Bs[2][BN * STR];

    const int tid = threadIdx.x;
    const int lane = tid & 31;
    const int g = lane >> 2, t = lane & 3;
    const int wid = tid >> 5;
    const int wm = (wid & 3) * 32;
    const int wn = (wid >> 2) * (BN / 2);
    const int rowBase = blockIdx.y * BM, colBase = blockIdx.x * BN;

    const int ar = tid >> 2, aq = tid & 3;       // A loader: rows ar, ar+64; k-quarter aq
    const int bp = tid & 15, bnc = tid >> 4;     // B loader: k-pair bp, n-chunk bnc
    const bool doB = (BN == 128) || (tid < 128);
    const int NCH = (3 * K) / BK;

    float acc[2][NT][4];
#pragma unroll
    for (int a = 0; a < 2; a++)
#pragma unroll
        for (int b = 0; b < NT; b++)
#pragma unroll
            for (int q = 0; q < 4; q++) acc[a][b][q] = 0.0f;

    uint4 ra0, ra1, rb0, rb1;
    const uint4 Z4 = make_uint4(0, 0, 0, 0);

#define FETCH(c) {                                                              \
    int k0 = (c) * BK; int seg = k0 / K; int kk = k0 - seg * K;                 \
    const __nv_bfloat16* Ap = (seg == 1) ? Alo : Ahi;                           \
    const __nv_bfloat16* Bp = (seg == 2) ? Blo : Bhi;                           \
    int r0 = rowBase + ar;                                                      \
    ra0 = (r0 < M)      ? *(const uint4*)(Ap + (size_t)r0 * K + kk + aq * 8) : Z4; \
    ra1 = (r0 + 64 < M) ? *(const uint4*)(Ap + (size_t)(r0 + 64) * K + kk + aq * 8) : Z4; \
    if (doB) {                                                                  \
        const __nv_bfloat16* bq = Bp + (size_t)(kk + 2 * bp) * N + colBase + bnc * 8; \
        rb0 = *(const uint4*)bq; rb1 = *(const uint4*)(bq + N);                 \
    } }

#define STORE(buf) {                                                            \
    *(uint4*)&As[buf][ar * STR + aq * 4] = ra0;                                 \
    *(uint4*)&As[buf][(ar + 64) * STR + aq * 4] = ra1;                          \
    if (doB) {                                                                  \
        const uint16_t* ea = (const uint16_t*)&rb0;                             \
        const uint16_t* eb = (const uint16_t*)&rb1;                             \
        for (int j = 0; j < 8; j++)                                             \
            Bs[buf][(bnc * 8 + j) * STR + bp] = (uint32_t)ea[j] | ((uint32_t)eb[j] << 16); \
    } }

    FETCH(0); STORE(0); __syncthreads();
    int cur = 0;
    for (int c = 0; c < NCH; c++) {
        if (c + 1 < NCH) FETCH(c + 1);
#pragma unroll
        for (int s8 = 0; s8 < 2; s8++) {
            const int kb = s8 * 8;
            uint32_t af[2][4];
#pragma unroll
            for (int mt = 0; mt < 2; mt++) {
                int m0 = wm + mt * 16 + g;
                af[mt][0] = As[cur][m0 * STR + kb + t];
                af[mt][1] = As[cur][(m0 + 8) * STR + kb + t];
                af[mt][2] = As[cur][m0 * STR + kb + t + 4];
                af[mt][3] = As[cur][(m0 + 8) * STR + kb + t + 4];
            }
#pragma unroll
            for (int nt = 0; nt < NT; nt++) {
                int n0 = wn + nt * 8 + g;
                uint32_t b0 = Bs[cur][n0 * STR + kb + t];
                uint32_t b1 = Bs[cur][n0 * STR + kb + t + 4];
#pragma unroll
                for (int mt = 0; mt < 2; mt++) {
                    asm volatile(
                        "mma.sync.aligned.m16n8k16.row.col.f32.bf16.bf16.f32 "
                        "{%0,%1,%2,%3},{%4,%5,%6,%7},{%8,%9},{%0,%1,%2,%3};"
                        : "+f"(acc[mt][nt][0]), "+f"(acc[mt][nt][1]),
                          "+f"(acc[mt][nt][2]), "+f"(acc[mt][nt][3])
                        : "r"(af[mt][0]), "r"(af[mt][1]), "r"(af[mt][2]), "r"(af[mt][3]),
                          "r"(b0), "r"(b1));
                }
            }
        }
        if (c + 1 < NCH) { int nxt = cur ^ 1; STORE(nxt); __syncthreads(); cur = nxt; }
    }
#undef FETCH
#undef STORE

    // epilogue: acc[mt][nt] = {C[g][2t], C[g][2t+1], C[g+8][2t], C[g+8][2t+1]}
#pragma unroll
    for (int mt = 0; mt < 2; mt++) {
#pragma unroll
        for (int half = 0; half < 2; half++) {
            int r = rowBase + wm + mt * 16 + g + half * 8;
            if (r >= M) continue;
#pragma unroll
            for (int nt = 0; nt < NT; nt++) {
                int cc = colBase + wn + nt * 8 + 2 * t;
                float v0 = acc[mt][nt][half * 2 + 0];
                float v1 = acc[mt][nt][half * 2 + 1];
                if (EPI == 1) {
                    v0 += bias[cc]; v1 += bias[cc + 1];
                    v0 = (v0 > 0.f) ? v0 : 0.01f * v0;
                    v1 = (v1 > 0.f) ? v1 : 0.01f * v1;
                    __nv_bfloat162 H, L;
                    split2(v0, v1, H, L);
                    *(__nv_bfloat162*)(Chi + (size_t)r * N + cc) = H;
                    *(__nv_bfloat162*)(Clo + (size_t)r * N + cc) = L;
                } else {
                    float2 o; o.x = v0; o.y = v1;
                    *(float2*)(Cf + (size_t)r * N + cc) = o;
                }
            }
        }
    }
}

// ---------------- launcher ----------------
extern "C" void kernel_launch(void* const* d_in, const int* in_sizes, int n_in,
                              void* d_out, int out_size) {
    const float* x  = (const float*)d_in[0];
    const void*  ei = d_in[1];
    const float* ew = (const float*)d_in[2];
    const float* W1 = (const float*)d_in[3];
    const float* b1 = (const float*)d_in[4];
    const float* W2 = (const float*)d_in[5];
    const float* b2 = (const float*)d_in[6];
    const float* W3 = (const float*)d_in[7];
    const float* b3 = (const float*)d_in[8];
    float* out = (float*)d_out;

    float *p_agg0, *p_t2, *p_a2, *p_t3;
    __nv_bfloat16 *p_a0hi, *p_a0lo, *p_h1hi, *p_h1lo, *p_a2hi, *p_a2lo;
    __nv_bfloat16 *p_w1hi, *p_w1lo, *p_w2hi, *p_w2lo, *p_w3hi, *p_w3lo;
    cudaGetSymbolAddress((void**)&p_agg0, g_agg0);
    cudaGetSymbolAddress((void**)&p_t2,   g_t2);
    cudaGetSymbolAddress((void**)&p_a2,   g_a2);
    cudaGetSymbolAddress((void**)&p_t3,   g_t3);
    cudaGetSymbolAddress((void**)&p_a0hi, g_a0hi);
    cudaGetSymbolAddress((void**)&p_a0lo, g_a0lo);
    cudaGetSymbolAddress((void**)&p_h1hi, g_h1hi);
    cudaGetSymbolAddress((void**)&p_h1lo, g_h1lo);
    cudaGetSymbolAddress((void**)&p_a2hi, g_a2hi);
    cudaGetSymbolAddress((void**)&p_a2lo, g_a2lo);
    cudaGetSymbolAddress((void**)&p_w1hi, g_w1hi);
    cudaGetSymbolAddress((void**)&p_w1lo, g_w1lo);
    cudaGetSymbolAddress((void**)&p_w2hi, g_w2hi);
    cudaGetSymbolAddress((void**)&p_w2lo, g_w2lo);
    cudaGetSymbolAddress((void**)&p_w3hi, g_w3hi);
    cudaGetSymbolAddress((void**)&p_w3lo, g_w3lo);

    // normalization
    k_init<<<(NN + 255) / 256, 256>>>();
    k_detect<<<1, 128>>>((const int*)ei);
    k_convert<<<(2 * NE + 255) / 256, 256>>>(ei);
    k_deg<<<(NE + 255) / 256, 256>>>(ew);
    k_dinv<<<(NN + 255) / 256, 256>>>();
    k_norm<<<(NE + 255) / 256, 256>>>(ew);

    // weight splits
    k_split<<<(F0 * F1 / 4 + 255) / 256, 256>>>(W1, p_w1hi, p_w1lo, F0 * F1 / 4);
    k_split<<<(F1 * F2 / 4 + 255) / 256, 256>>>(W2, p_w2hi, p_w2lo, F1 * F2 / 4);
    k_split<<<(F2 * F3 / 4 + 255) / 256, 256>>>(W3, p_w3hi, p_w3lo, F2 * F3 / 4);

    // ---- layer 1: aggregate(512), split, GEMM(512->2048)+bias+leaky -> bf16 split ----
    // A(XW) == (AX)W  -> aggregate in the 512-dim input space
    k_selfloop<F0><<<(NN * (F0 / 4) + 255) / 256, 256>>>(x, p_agg0);
    k_edgeagg<F0><<<(NE * (F0 / 4) + 255) / 256, 256>>>(x, p_agg0);
    k_split<<<(NN * F0 / 4 + 255) / 256, 256>>>(p_agg0, p_a0hi, p_a0lo, NN * F0 / 4);
    gemm_b3<128, 1><<<dim3(F1 / 128, (NN + 127) / 128), 256>>>(
        NN, F1, F0, p_a0hi, p_a0lo, p_w1hi, p_w1lo, b1, nullptr, p_h1hi, p_h1lo);

    // ---- layer 2: GEMM(2048->256), aggregate, bias+relu -> bf16 split ----
    gemm_b3<128, 0><<<dim3(F2 / 128, (NN + 127) / 128), 256>>>(
        NN, F2, F1, p_h1hi, p_h1lo, p_w2hi, p_w2lo, nullptr, p_t2, nullptr, nullptr);
    k_selfloop<F2><<<(NN * (F2 / 4) + 255) / 256, 256>>>(p_t2, p_a2);
    k_edgeagg<F2><<<(NE * (F2 / 4) + 255) / 256, 256>>>(p_t2, p_a2);
    k_biassplit<F2><<<(NN * (F2 / 4) + 255) / 256, 256>>>(p_a2, b2, p_a2hi, p_a2lo);

    // ---- layer 3: GEMM(256->64), aggregate, bias+relu ----
    gemm_b3<64, 0><<<dim3(F3 / 64, (NN + 127) / 128), 256>>>(
        NN, F3, F2, p_a2hi, p_a2lo, p_w3hi, p_w3lo, nullptr, p_t3, nullptr, nullptr);
    k_selfloop<F3><<<(NN * (F3 / 4) + 255) / 256, 256>>>(p_t3, out);
    k_edgeagg<F3><<<(NE * (F3 / 4) + 255) / 256, 256>>>(p_t3, out);
    k_biasrelu<F3><<<(NN * (F3 / 4) + 255) / 256, 256>>>(out, b3);
}